// round 2
// baseline (speedup 1.0000x reference)
#include <cuda_runtime.h>
#include <cstdint>
#include <cstddef>

#define B_ 32
#define T_ 2048
#define W_ 1024
#define G_ 16
#define D_ 64
#define INV_TM1 (1.0f/2047.0f)

// ---------------- scratch (static device memory; no allocations) ----------------
__device__ float g_cov[(size_t)B_ * W_ * W_];   // 128 MB: raw centered-sum cov (upper tiles valid)
__device__ float g_mean[B_ * W_];
__device__ float g_rstd[B_ * W_];
__device__ float g_partial[B_ * G_];

// ---------------- 1) per-(batch, column) mean + 1/std over T ----------------
__global__ __launch_bounds__(256) void meanstd_kernel(const float* __restrict__ x) {
    int b = blockIdx.y;
    int w = blockIdx.x * 256 + threadIdx.x;
    const float* p = x + (size_t)b * (T_ * W_) + w;
    float s1 = 0.f, s2 = 0.f;
#pragma unroll 8
    for (int t = 0; t < T_; ++t) {
        float v = __ldg(p + (size_t)t * W_);
        s1 += v;
        s2 = fmaf(v, v, s2);
    }
    float mean  = s1 * (1.0f / T_);
    float sumc2 = fmaxf(s2 - s1 * mean, 0.f);          // sum of centered squares
    float sd    = sqrtf(sumc2 * INV_TM1);              // std = sqrt(sumc2/(T-1))
    g_mean[b * W_ + w] = mean;
    g_rstd[b * W_ + w] = (sd > 0.f) ? (1.0f / sd) : 0.f;
}

// ---------------- 2) cov GEMM: C_b = Ac^T Ac, upper 128x128 tiles only ----------------
__global__ __launch_bounds__(256) void cov_gemm_kernel(const float* __restrict__ x) {
    int b = blockIdx.y;
    // map linear upper-triangular tile index -> (bi, bj), 8x8 tile grid, 36 tiles
    int rem = blockIdx.x, bi = 0, n = 8;
    while (rem >= n) { rem -= n; --n; ++bi; }
    int bj = bi + rem;

    __shared__ __align__(16) float As[2][8][128];
    __shared__ __align__(16) float Bs[2][8][128];

    const float* Xb = x + (size_t)b * (T_ * W_);
    int tid = threadIdx.x;
    int ldr = tid >> 5, ldc = tid & 31;

    const float* gU = Xb + (size_t)ldr * W_ + bi * 128 + ldc * 4;
    const float* gV = Xb + (size_t)ldr * W_ + bj * 128 + ldc * 4;
    float4 mu = *(const float4*)(g_mean + b * W_ + bi * 128 + ldc * 4);
    float4 mv = *(const float4*)(g_mean + b * W_ + bj * 128 + ldc * 4);

    float4 u = *(const float4*)gU;
    float4 v = *(const float4*)gV;
    *(float4*)&As[0][ldr][ldc * 4] = make_float4(u.x - mu.x, u.y - mu.y, u.z - mu.z, u.w - mu.w);
    *(float4*)&Bs[0][ldr][ldc * 4] = make_float4(v.x - mv.x, v.y - mv.y, v.z - mv.z, v.w - mv.w);
    __syncthreads();

    int tx = tid & 15, ty = tid >> 4;
    float acc[8][8];
#pragma unroll
    for (int r = 0; r < 8; ++r)
#pragma unroll
        for (int c = 0; c < 8; ++c) acc[r][c] = 0.f;

    const int NIT = T_ / 8;  // 256
    for (int it = 0; it < NIT; ++it) {
        int cur = it & 1;
        if (it + 1 < NIT) {  // global prefetch into registers
            u = *(const float4*)(gU + (size_t)(it + 1) * 8 * W_);
            v = *(const float4*)(gV + (size_t)(it + 1) * 8 * W_);
        }
#pragma unroll
        for (int k = 0; k < 8; ++k) {
            float a[8], bb[8];
            *(float4*)&a[0]  = *(float4*)&As[cur][k][ty * 8];
            *(float4*)&a[4]  = *(float4*)&As[cur][k][ty * 8 + 4];
            *(float4*)&bb[0] = *(float4*)&Bs[cur][k][tx * 8];
            *(float4*)&bb[4] = *(float4*)&Bs[cur][k][tx * 8 + 4];
#pragma unroll
            for (int r = 0; r < 8; ++r)
#pragma unroll
                for (int c = 0; c < 8; ++c)
                    acc[r][c] = fmaf(a[r], bb[c], acc[r][c]);
        }
        if (it + 1 < NIT) {
            int nxt = cur ^ 1;
            *(float4*)&As[nxt][ldr][ldc * 4] = make_float4(u.x - mu.x, u.y - mu.y, u.z - mu.z, u.w - mu.w);
            *(float4*)&Bs[nxt][ldr][ldc * 4] = make_float4(v.x - mv.x, v.y - mv.y, v.z - mv.z, v.w - mv.w);
        }
        __syncthreads();
    }

    float* Cb = g_cov + (size_t)b * (W_ * W_) + (size_t)(bi * 128 + ty * 8) * W_ + bj * 128 + tx * 8;
#pragma unroll
    for (int r = 0; r < 8; ++r) {
        *(float4*)(Cb + (size_t)r * W_)     = *(float4*)&acc[r][0];
        *(float4*)(Cb + (size_t)r * W_ + 4) = *(float4*)&acc[r][4];
    }
}

// ---------------- 3) EMA scan epilogue over batches ----------------
__global__ __launch_bounds__(256) void ema_kernel(const float* __restrict__ ema_in,
                                                  float* __restrict__ ema_out) {
    int idx = blockIdx.x * 256 + threadIdx.x;
    int w = idx >> 10, v = idx & 1023;
    int lo = min(w, v), hi = max(w, v);           // cov valid only in upper triangle
    const float* cp = g_cov + (size_t)lo * W_ + hi;
    float e = __ldg(ema_in + idx);
#pragma unroll 4
    for (int b = 0; b < B_; ++b) {
        float c  = __ldg(cp + (size_t)b * (W_ * W_)) * INV_TM1;
        float rw = g_rstd[b * W_ + w];
        float rv = g_rstd[b * W_ + v];
        float corr = c * rw * rv;                 // == c/(sw*sv+eps) to 1e-8 rel
        corr = fminf(1.f, fmaxf(-1.f, corr));
        if (fabsf(corr) > 0.5f) e = 0.9f * e + 0.1f * corr;
    }
    ema_out[idx] = e;
}

// ---------------- 4) per-(g,b) off-diagonal |corr| partial sums ----------------
__global__ __launch_bounds__(256) void corr_partial_kernel() {
    int g = blockIdx.x, b = blockIdx.y;
    const float* covb = g_cov + (size_t)b * (W_ * W_);
    const float* rs   = g_rstd + b * W_;
    int tid = threadIdx.x;
    float s = 0.f;
    for (int i = tid; i < D_ * D_; i += 256) {
        int d = i >> 6, e = i & 63;
        if (d == e) continue;                      // off-diagonal only (== sum - trace)
        int w = g * 64 + d, v = g * 64 + e;        // same 128-tile -> both orders stored
        float c = covb[(size_t)w * W_ + v] * INV_TM1;
        float corr = fminf(1.f, fmaxf(-1.f, c * rs[w] * rs[v]));
        s += fabsf(corr);
    }
    __shared__ float red[256];
    red[tid] = s;
    __syncthreads();
    for (int off = 128; off > 0; off >>= 1) {
        if (tid < off) red[tid] += red[tid + off];
        __syncthreads();
    }
    if (tid == 0) g_partial[b * G_ + g] = red[0];
}

__global__ void corr_final_kernel(float* __restrict__ out_corr) {
    int g = threadIdx.x;
    if (g < G_) {
        float s = 0.f;
        for (int b = 0; b < B_; ++b) s += g_partial[b * G_ + g];  // fixed order: deterministic
        out_corr[g] = s * (1.0f / ((float)(D_ * D_ - D_) * (float)B_));
    }
}

// ---------------- 5) expert MLP: D->16(relu)->1 per group ----------------
// Block: 256 threads = 4 groups x 64 thread-rows, 2 t-rows per thread.
// grid = (B*T/128, 4 group-quads). W1 quad staged in 16KB static smem.
__global__ __launch_bounds__(256) void mlp_kernel(const float* __restrict__ x,
                                                  const float* __restrict__ W1,
                                                  const float* __restrict__ b1,
                                                  const float* __restrict__ W2,
                                                  const float* __restrict__ b2,
                                                  float* __restrict__ out) {
    __shared__ __align__(16) float W1s[4096];
    __shared__ float b1s[64], W2s[64], b2s[4];
    int tid = threadIdx.x;
    int gq = blockIdx.y;
    for (int i = tid; i < 1024; i += 256)
        ((float4*)W1s)[i] = ((const float4*)(W1 + (size_t)gq * 4096))[i];
    if (tid < 64) { b1s[tid] = b1[gq * 64 + tid]; W2s[tid] = W2[gq * 64 + tid]; }
    if (tid < 4) b2s[tid] = b2[gq * 4 + tid];
    __syncthreads();

    int gsub = tid & 3, tr = tid >> 2;             // tr in [0,64)
    int g = gq * 4 + gsub;
    size_t row0 = (size_t)blockIdx.x * 128 + tr * 2;
    const float4* xp0 = (const float4*)(x + row0 * W_ + g * 64);
    const float4* xp1 = (const float4*)(x + (row0 + 1) * W_ + g * 64);

    float h0[16], h1[16];
#pragma unroll
    for (int h = 0; h < 16; ++h) { h0[h] = b1s[gsub * 16 + h]; h1[h] = h0[h]; }

#pragma unroll 4
    for (int d4 = 0; d4 < 16; ++d4) {
        float4 xa = __ldg(xp0 + d4);
        float4 xb = __ldg(xp1 + d4);
#pragma unroll
        for (int h = 0; h < 16; ++h) {
            float4 wv = *(float4*)&W1s[(gsub * 16 + h) * 64 + d4 * 4];
            h0[h] = fmaf(wv.x, xa.x, h0[h]); h0[h] = fmaf(wv.y, xa.y, h0[h]);
            h0[h] = fmaf(wv.z, xa.z, h0[h]); h0[h] = fmaf(wv.w, xa.w, h0[h]);
            h1[h] = fmaf(wv.x, xb.x, h1[h]); h1[h] = fmaf(wv.y, xb.y, h1[h]);
            h1[h] = fmaf(wv.z, xb.z, h1[h]); h1[h] = fmaf(wv.w, xb.w, h1[h]);
        }
    }
    float o0 = b2s[gsub], o1 = b2s[gsub];
#pragma unroll
    for (int h = 0; h < 16; ++h) {
        o0 += W2s[gsub * 16 + h] * fmaxf(h0[h], 0.f);
        o1 += W2s[gsub * 16 + h] * fmaxf(h1[h], 0.f);
    }
    out[row0 * G_ + g]       = o0;
    out[(row0 + 1) * G_ + g] = o1;
}

// ---------------- launch ----------------
extern "C" void kernel_launch(void* const* d_in, const int* in_sizes, int n_in,
                              void* d_out, int out_size) {
    const float* x   = (const float*)d_in[0];
    const float* ema = (const float*)d_in[1];
    const float* W1  = (const float*)d_in[2];
    const float* b1  = (const float*)d_in[3];
    const float* W2  = (const float*)d_in[4];
    const float* b2  = (const float*)d_in[5];

    float* out      = (float*)d_out;                      // (B,T,G) = 1048576
    float* out_corr = out + (size_t)B_ * T_ * G_;         // (G,)    = 16
    float* out_ema  = out_corr + G_;                      // (W,W)   = 1048576

    meanstd_kernel<<<dim3(W_ / 256, B_), 256>>>(x);
    cov_gemm_kernel<<<dim3(36, B_), 256>>>(x);
    ema_kernel<<<(W_ * W_) / 256, 256>>>(ema, out_ema);
    corr_partial_kernel<<<dim3(G_, B_), 256>>>();
    corr_final_kernel<<<1, 32>>>(out_corr);
    mlp_kernel<<<dim3(B_ * T_ / 128, 4), 256>>>(x, W1, b1, W2, b2, out);
}

// round 3
// speedup vs baseline: 2.4964x; 2.4964x over previous
#include <cuda_runtime.h>
#include <cuda_bf16.h>
#include <cstdint>
#include <cstddef>

#define B_ 32
#define T_ 2048
#define W_ 1024
#define G_ 16
#define D_ 64
#define INV_TM1 (1.0f/2047.0f)

// ---------------- scratch (static device memory; no allocations) ----------------
__device__ float g_cov[(size_t)B_ * W_ * W_];           // 128 MB raw centered-sum cov (FULL matrix)
__device__ __nv_bfloat16 g_xc[(size_t)B_ * T_ * W_];    // 128 MB centered bf16 input
__device__ float g_mean[B_ * W_];
__device__ float g_rstd[B_ * W_];
__device__ float g_partial[B_ * G_];

// ---------------- 1) per-(batch, column) mean over T ----------------
__global__ __launch_bounds__(256) void mean_kernel(const float* __restrict__ x) {
    int b = blockIdx.y;
    int w = blockIdx.x * 256 + threadIdx.x;
    const float* p = x + (size_t)b * (T_ * W_) + w;
    float s1 = 0.f;
#pragma unroll 8
    for (int t = 0; t < T_; ++t) s1 += __ldg(p + (size_t)t * W_);
    g_mean[b * W_ + w] = s1 * (1.0f / T_);
}

// ---------------- 2) center + convert to bf16 ----------------
__global__ __launch_bounds__(256) void center_kernel(const float* __restrict__ x) {
    size_t i4 = ((size_t)blockIdx.x * 256 + threadIdx.x) * 4;
    int w  = (int)(i4 & (W_ - 1));
    int bw = (int)(i4 >> 21) * W_ + w;           // T_*W_ = 2^21
    float4 v = *(const float4*)(x + i4);
    float4 m = *(const float4*)(g_mean + bw);
    __nv_bfloat162 lo, hi;
    lo.x = __float2bfloat16_rn(v.x - m.x); lo.y = __float2bfloat16_rn(v.y - m.y);
    hi.x = __float2bfloat16_rn(v.z - m.z); hi.y = __float2bfloat16_rn(v.w - m.w);
    uint2 u;
    u.x = *(uint32_t*)&lo; u.y = *(uint32_t*)&hi;
    *(uint2*)(g_xc + i4) = u;
}

// ---------------- 3) bf16 tensor-core cov GEMM: C_b = Xc^T Xc (full 128x128 tiles) ----------------
#define KS  32   // K rows per pipeline stage
#define NST 3    // pipeline stages (3 * 2 tiles * 8KB = 48KB static smem)

__device__ __forceinline__ void cp16(uint32_t saddr, const void* gptr) {
    asm volatile("cp.async.cg.shared.global [%0], [%1], 16;\n" :: "r"(saddr), "l"(gptr));
}

__global__ __launch_bounds__(256, 2) void cov_mma_kernel() {
    int b  = blockIdx.y;
    int bi = blockIdx.x >> 3, bj = blockIdx.x & 7;

    __shared__ __align__(1024) unsigned char smem_raw[NST * 16384];
    uint32_t sbase = (uint32_t)__cvta_generic_to_shared(smem_raw);

    const __nv_bfloat16* XU = g_xc + (size_t)b * T_ * W_ + bi * 128;
    const __nv_bfloat16* XV = g_xc + (size_t)b * T_ * W_ + bj * 128;

    int tid = threadIdx.x;

    // prologue: load stages 0..NST-2
    for (int s = 0; s < NST - 1; ++s) {
        uint32_t sU = sbase + s * 16384, sV = sU + 8192;
#pragma unroll
        for (int i = 0; i < 2; ++i) {
            int c = tid + i * 256;
            int t = c >> 4, cb = c & 15;
            uint32_t o = (uint32_t)(t * 256 + ((cb ^ (t & 7)) << 4));
            cp16(sU + o, XU + (size_t)(s * KS + t) * W_ + cb * 8);
            cp16(sV + o, XV + (size_t)(s * KS + t) * W_ + cb * 8);
        }
        asm volatile("cp.async.commit_group;\n");
    }

    float acc[4][4][4];
#pragma unroll
    for (int a = 0; a < 4; ++a)
#pragma unroll
        for (int c = 0; c < 4; ++c)
#pragma unroll
            for (int r = 0; r < 4; ++r) acc[a][c][r] = 0.f;

    int lane = tid & 31, wid = tid >> 5;
    int wm = wid & 1, wn = wid >> 1;                      // warp tile: m64 x n32, grid 2x4
    int arow = (lane & 7) + ((lane >> 4) << 3);           // A trans-ldmatrix lane row
    int acbo = (lane >> 3) & 1;                           // A lane col-block offset
    int brow = (lane & 7) + (((lane >> 3) & 1) << 3);     // B trans-ldmatrix lane row
    int bcbo = lane >> 4;                                 // B lane col-block offset

    const int NKB = T_ / KS;  // 64
    for (int kb = 0; kb < NKB; ++kb) {
        asm volatile("cp.async.wait_group 1;\n");
        __syncthreads();  // stage kb visible to all; slot (kb-1)%NST free to overwrite

        int nk = kb + NST - 1;
        if (nk < NKB) {
            int s = nk % NST;
            uint32_t sU = sbase + s * 16384, sV = sU + 8192;
#pragma unroll
            for (int i = 0; i < 2; ++i) {
                int c = tid + i * 256;
                int t = c >> 4, cb = c & 15;
                uint32_t o = (uint32_t)(t * 256 + ((cb ^ (t & 7)) << 4));
                cp16(sU + o, XU + (size_t)(nk * KS + t) * W_ + cb * 8);
                cp16(sV + o, XV + (size_t)(nk * KS + t) * W_ + cb * 8);
            }
            asm volatile("cp.async.commit_group;\n");
        }

        int st = kb % NST;
        uint32_t sU = sbase + st * 16384, sV = sU + 8192;
#pragma unroll
        for (int ks = 0; ks < KS / 16; ++ks) {
            int t0 = ks * 16;
            uint32_t a[4][4];
#pragma unroll
            for (int mi = 0; mi < 4; ++mi) {
                int cbA = ((wm * 64 + mi * 16) >> 3) + acbo;
                int row = t0 + arow;
                uint32_t addr = sU + row * 256 + ((cbA ^ (row & 7)) << 4);
                asm volatile("ldmatrix.sync.aligned.m8n8.x4.trans.shared.b16 {%0,%1,%2,%3}, [%4];\n"
                    : "=r"(a[mi][0]), "=r"(a[mi][1]), "=r"(a[mi][2]), "=r"(a[mi][3]) : "r"(addr));
            }
            uint32_t bfr[4][2];
#pragma unroll
            for (int nb = 0; nb < 2; ++nb) {
                int cbB = ((wn * 32 + nb * 16) >> 3) + bcbo;
                int row = t0 + brow;
                uint32_t addr = sV + row * 256 + ((cbB ^ (row & 7)) << 4);
                uint32_t r0, r1, r2, r3;
                asm volatile("ldmatrix.sync.aligned.m8n8.x4.trans.shared.b16 {%0,%1,%2,%3}, [%4];\n"
                    : "=r"(r0), "=r"(r1), "=r"(r2), "=r"(r3) : "r"(addr));
                bfr[nb * 2][0] = r0; bfr[nb * 2][1] = r1;
                bfr[nb * 2 + 1][0] = r2; bfr[nb * 2 + 1][1] = r3;
            }
#pragma unroll
            for (int mi = 0; mi < 4; ++mi)
#pragma unroll
                for (int ni = 0; ni < 4; ++ni)
                    asm volatile("mma.sync.aligned.m16n8k16.row.col.f32.bf16.bf16.f32 "
                        "{%0,%1,%2,%3},{%4,%5,%6,%7},{%8,%9},{%0,%1,%2,%3};\n"
                        : "+f"(acc[mi][ni][0]), "+f"(acc[mi][ni][1]),
                          "+f"(acc[mi][ni][2]), "+f"(acc[mi][ni][3])
                        : "r"(a[mi][0]), "r"(a[mi][1]), "r"(a[mi][2]), "r"(a[mi][3]),
                          "r"(bfr[ni][0]), "r"(bfr[ni][1]));
        }
    }

    float* Cb = g_cov + (size_t)b * W_ * W_;
    int g = lane >> 2, tg = lane & 3;
#pragma unroll
    for (int mi = 0; mi < 4; ++mi) {
        int m = bi * 128 + wm * 64 + mi * 16 + g;
#pragma unroll
        for (int ni = 0; ni < 4; ++ni) {
            int n = bj * 128 + wn * 32 + ni * 8 + tg * 2;
            *(float2*)(Cb + (size_t)m * W_ + n)       = make_float2(acc[mi][ni][0], acc[mi][ni][1]);
            *(float2*)(Cb + (size_t)(m + 8) * W_ + n) = make_float2(acc[mi][ni][2], acc[mi][ni][3]);
        }
    }
}

// ---------------- 4) rstd from GEMM diagonal (bf16-consistent: corr_ii == 1 exactly) ----------------
__global__ __launch_bounds__(256) void rstd_kernel() {
    int i = blockIdx.x * 256 + threadIdx.x;    // 32768
    int b = i >> 10, w = i & 1023;
    float s = g_cov[(size_t)b * W_ * W_ + (size_t)w * W_ + w] * INV_TM1;
    g_rstd[i] = (s > 0.f) ? rsqrtf(s) : 0.f;
}

// ---------------- 5) EMA scan epilogue over batches (fully coalesced now) ----------------
__global__ __launch_bounds__(256) void ema_kernel(const float* __restrict__ ema_in,
                                                  float* __restrict__ ema_out) {
    int idx = blockIdx.x * 256 + threadIdx.x;
    int w = idx >> 10, v = idx & 1023;
    const float* cp = g_cov + (size_t)w * W_ + v;
    float e = __ldg(ema_in + idx);
#pragma unroll 4
    for (int b = 0; b < B_; ++b) {
        float c  = __ldg(cp + (size_t)b * (W_ * W_)) * INV_TM1;
        float rw = g_rstd[b * W_ + w];
        float rv = g_rstd[b * W_ + v];
        float corr = c * rw * rv;                 // == c/(sw*sv+eps) to ~1e-8 rel
        corr = fminf(1.f, fmaxf(-1.f, corr));
        if (fabsf(corr) > 0.5f) e = 0.9f * e + 0.1f * corr;
    }
    ema_out[idx] = e;
}

// ---------------- 6) per-(g,b) off-diagonal |corr| partial sums ----------------
__global__ __launch_bounds__(256) void corr_partial_kernel() {
    int g = blockIdx.x, b = blockIdx.y;
    const float* covb = g_cov + (size_t)b * (W_ * W_);
    const float* rs   = g_rstd + b * W_;
    int tid = threadIdx.x;
    float s = 0.f;
    for (int i = tid; i < D_ * D_; i += 256) {
        int d = i >> 6, e = i & 63;
        if (d == e) continue;
        int w = g * 64 + d, v = g * 64 + e;
        float c = covb[(size_t)w * W_ + v] * INV_TM1;
        float corr = fminf(1.f, fmaxf(-1.f, c * rs[w] * rs[v]));
        s += fabsf(corr);
    }
    __shared__ float red[256];
    red[tid] = s;
    __syncthreads();
    for (int off = 128; off > 0; off >>= 1) {
        if (tid < off) red[tid] += red[tid + off];
        __syncthreads();
    }
    if (tid == 0) g_partial[b * G_ + g] = red[0];
}

__global__ void corr_final_kernel(float* __restrict__ out_corr) {
    int g = threadIdx.x;
    if (g < G_) {
        float s = 0.f;
        for (int b = 0; b < B_; ++b) s += g_partial[b * G_ + g];  // fixed order: deterministic
        out_corr[g] = s * (1.0f / ((float)(D_ * D_ - D_) * (float)B_));
    }
}

// ---------------- 7) expert MLP: D->16(relu)->1 per group ----------------
__global__ __launch_bounds__(256) void mlp_kernel(const float* __restrict__ x,
                                                  const float* __restrict__ W1,
                                                  const float* __restrict__ b1,
                                                  const float* __restrict__ W2,
                                                  const float* __restrict__ b2,
                                                  float* __restrict__ out) {
    __shared__ __align__(16) float W1s[4096];
    __shared__ float b1s[64], W2s[64], b2s[4];
    int tid = threadIdx.x;
    int gq = blockIdx.y;
    for (int i = tid; i < 1024; i += 256)
        ((float4*)W1s)[i] = ((const float4*)(W1 + (size_t)gq * 4096))[i];
    if (tid < 64) { b1s[tid] = b1[gq * 64 + tid]; W2s[tid] = W2[gq * 64 + tid]; }
    if (tid < 4) b2s[tid] = b2[gq * 4 + tid];
    __syncthreads();

    int gsub = tid & 3, tr = tid >> 2;
    int g = gq * 4 + gsub;
    size_t row0 = (size_t)blockIdx.x * 128 + tr * 2;
    const float4* xp0 = (const float4*)(x + row0 * W_ + g * 64);
    const float4* xp1 = (const float4*)(x + (row0 + 1) * W_ + g * 64);

    float h0[16], h1[16];
#pragma unroll
    for (int h = 0; h < 16; ++h) { h0[h] = b1s[gsub * 16 + h]; h1[h] = h0[h]; }

#pragma unroll 4
    for (int d4 = 0; d4 < 16; ++d4) {
        float4 xa = __ldg(xp0 + d4);
        float4 xb = __ldg(xp1 + d4);
#pragma unroll
        for (int h = 0; h < 16; ++h) {
            float4 wv = *(float4*)&W1s[(gsub * 16 + h) * 64 + d4 * 4];
            h0[h] = fmaf(wv.x, xa.x, h0[h]); h0[h] = fmaf(wv.y, xa.y, h0[h]);
            h0[h] = fmaf(wv.z, xa.z, h0[h]); h0[h] = fmaf(wv.w, xa.w, h0[h]);
            h1[h] = fmaf(wv.x, xb.x, h1[h]); h1[h] = fmaf(wv.y, xb.y, h1[h]);
            h1[h] = fmaf(wv.z, xb.z, h1[h]); h1[h] = fmaf(wv.w, xb.w, h1[h]);
        }
    }
    float o0 = b2s[gsub], o1 = b2s[gsub];
#pragma unroll
    for (int h = 0; h < 16; ++h) {
        o0 += W2s[gsub * 16 + h] * fmaxf(h0[h], 0.f);
        o1 += W2s[gsub * 16 + h] * fmaxf(h1[h], 0.f);
    }
    out[row0 * G_ + g]       = o0;
    out[(row0 + 1) * G_ + g] = o1;
}

// ---------------- launch ----------------
extern "C" void kernel_launch(void* const* d_in, const int* in_sizes, int n_in,
                              void* d_out, int out_size) {
    (void)in_sizes; (void)n_in; (void)out_size;
    const float* x   = (const float*)d_in[0];
    const float* ema = (const float*)d_in[1];
    const float* W1  = (const float*)d_in[2];
    const float* b1  = (const float*)d_in[3];
    const float* W2  = (const float*)d_in[4];
    const float* b2  = (const float*)d_in[5];

    float* out      = (float*)d_out;                      // (B,T,G) = 1048576
    float* out_corr = out + (size_t)B_ * T_ * G_;         // (G,)    = 16
    float* out_ema  = out_corr + G_;                      // (W,W)   = 1048576

    mean_kernel<<<dim3(W_ / 256, B_), 256>>>(x);
    center_kernel<<<(int)((size_t)B_ * T_ * W_ / 4 / 256), 256>>>(x);
    cov_mma_kernel<<<dim3(64, B_), 256>>>();
    rstd_kernel<<<(B_ * W_) / 256, 256>>>();
    ema_kernel<<<(W_ * W_) / 256, 256>>>(ema, out_ema);
    corr_partial_kernel<<<dim3(G_, B_), 256>>>();
    corr_final_kernel<<<1, 32>>>(out_corr);
    mlp_kernel<<<dim3(B_ * T_ / 128, 4), 256>>>(x, W1, b1, W2, b2, out);
}

// round 5
// speedup vs baseline: 2.9831x; 1.1950x over previous
#include <cuda_runtime.h>
#include <cuda_bf16.h>
#include <cstdint>
#include <cstddef>

#define B_ 32
#define T_ 2048
#define W_ 1024
#define G_ 16
#define D_ 64
#define INV_TM1 (1.0f/2047.0f)

// ---------------- scratch (static device memory; no allocations) ----------------
__device__ float g_cov[(size_t)B_ * W_ * W_];           // raw (uncentered) bf16 Gram, upper tiles only
__device__ __nv_bfloat16 g_xc[(size_t)B_ * T_ * W_];    // bf16(x), uncentered, [b][t][w]
__device__ float g_mean[B_ * W_];                       // mean of bf16 values over T
__device__ float g_rstd[B_ * W_];
__device__ float g_partial[B_ * G_];

// ---------------- 1) x -> bf16 (uncentered, elementwise) ----------------
__global__ __launch_bounds__(256) void tobf16_kernel(const float* __restrict__ x) {
    size_t i4 = ((size_t)blockIdx.x * 256 + threadIdx.x) * 4;
    float4 v = *(const float4*)(x + i4);
    __nv_bfloat162 lo, hi;
    lo.x = __float2bfloat16_rn(v.x); lo.y = __float2bfloat16_rn(v.y);
    hi.x = __float2bfloat16_rn(v.z); hi.y = __float2bfloat16_rn(v.w);
    uint2 u;
    u.x = *(uint32_t*)&lo; u.y = *(uint32_t*)&hi;
    *(uint2*)(g_xc + i4) = u;
}

// ---------------- 2) per-(batch, column) mean of bf16 values over T ----------------
__global__ __launch_bounds__(256) void mean_kernel() {
    int b = blockIdx.y;
    int w = blockIdx.x * 256 + threadIdx.x;
    const __nv_bfloat16* p = g_xc + (size_t)b * (T_ * W_) + w;
    float s1 = 0.f;
#pragma unroll 8
    for (int t = 0; t < T_; ++t) s1 += __bfloat162float(__ldg(p + (size_t)t * W_));
    g_mean[b * W_ + w] = s1 * (1.0f / T_);
}

// ---------------- 3) bf16 mma.sync Gram: C_b = X^T X, upper 128x128 tiles only ----------------
#define KS  32   // K rows per pipeline stage
#define NST 3    // pipeline stages (3 * 2 tiles * 8KB = 48KB static smem)

__device__ __forceinline__ void cp16(uint32_t saddr, const void* gptr) {
    asm volatile("cp.async.cg.shared.global [%0], [%1], 16;\n" :: "r"(saddr), "l"(gptr));
}

__global__ __launch_bounds__(256, 2) void cov_mma_kernel() {
    int b = blockIdx.y;
    // upper-triangular tile index -> (bi, bj), 8x8 grid, 36 tiles
    int rem = blockIdx.x, bi = 0, n = 8;
    while (rem >= n) { rem -= n; --n; ++bi; }
    int bj = bi + rem;
    bool diag = (bi == bj);

    __shared__ __align__(1024) unsigned char smem_raw[NST * 16384];
    uint32_t sbase = (uint32_t)__cvta_generic_to_shared(smem_raw);

    const __nv_bfloat16* XU = g_xc + (size_t)b * T_ * W_ + bi * 128;
    const __nv_bfloat16* XV = g_xc + (size_t)b * T_ * W_ + bj * 128;

    int tid = threadIdx.x;

    // prologue: load stages 0..NST-2
    for (int s = 0; s < NST - 1; ++s) {
        uint32_t sU = sbase + s * 16384, sV = sU + 8192;
#pragma unroll
        for (int i = 0; i < 2; ++i) {
            int c = tid + i * 256;
            int t = c >> 4, cb = c & 15;
            uint32_t o = (uint32_t)(t * 256 + ((cb ^ (t & 7)) << 4));
            cp16(sU + o, XU + (size_t)(s * KS + t) * W_ + cb * 8);
            if (!diag) cp16(sV + o, XV + (size_t)(s * KS + t) * W_ + cb * 8);
        }
        asm volatile("cp.async.commit_group;\n");
    }

    float acc[4][4][4];
#pragma unroll
    for (int a = 0; a < 4; ++a)
#pragma unroll
        for (int c = 0; c < 4; ++c)
#pragma unroll
            for (int r = 0; r < 4; ++r) acc[a][c][r] = 0.f;

    int lane = tid & 31, wid = tid >> 5;
    int wm = wid & 1, wn = wid >> 1;                      // warp tile: m64 x n32, grid 2x4
    int arow = (lane & 7) + ((lane >> 4) << 3);           // A trans-ldmatrix lane row
    int acbo = (lane >> 3) & 1;
    int brow = (lane & 7) + (((lane >> 3) & 1) << 3);     // B trans-ldmatrix lane row
    int bcbo = lane >> 4;

    const int NKB = T_ / KS;  // 64
    for (int kb = 0; kb < NKB; ++kb) {
        asm volatile("cp.async.wait_group 1;\n");
        __syncthreads();

        int nk = kb + NST - 1;
        if (nk < NKB) {
            int s = nk % NST;
            uint32_t sU = sbase + s * 16384, sV = sU + 8192;
#pragma unroll
            for (int i = 0; i < 2; ++i) {
                int c = tid + i * 256;
                int t = c >> 4, cb = c & 15;
                uint32_t o = (uint32_t)(t * 256 + ((cb ^ (t & 7)) << 4));
                cp16(sU + o, XU + (size_t)(nk * KS + t) * W_ + cb * 8);
                if (!diag) cp16(sV + o, XV + (size_t)(nk * KS + t) * W_ + cb * 8);
            }
            asm volatile("cp.async.commit_group;\n");
        }

        int st = kb % NST;
        uint32_t sU = sbase + st * 16384;
        uint32_t sVd = diag ? sU : (sU + 8192);
#pragma unroll
        for (int ks = 0; ks < KS / 16; ++ks) {
            int t0 = ks * 16;
            uint32_t a[4][4];
#pragma unroll
            for (int mi = 0; mi < 4; ++mi) {
                int cbA = ((wm * 64 + mi * 16) >> 3) + acbo;
                int row = t0 + arow;
                uint32_t addr = sU + row * 256 + ((cbA ^ (row & 7)) << 4);
                asm volatile("ldmatrix.sync.aligned.m8n8.x4.trans.shared.b16 {%0,%1,%2,%3}, [%4];\n"
                    : "=r"(a[mi][0]), "=r"(a[mi][1]), "=r"(a[mi][2]), "=r"(a[mi][3]) : "r"(addr));
            }
            uint32_t bfr[4][2];
#pragma unroll
            for (int nb = 0; nb < 2; ++nb) {
                int cbB = ((wn * 32 + nb * 16) >> 3) + bcbo;
                int row = t0 + brow;
                uint32_t addr = sVd + row * 256 + ((cbB ^ (row & 7)) << 4);
                uint32_t r0, r1, r2, r3;
                asm volatile("ldmatrix.sync.aligned.m8n8.x4.trans.shared.b16 {%0,%1,%2,%3}, [%4];\n"
                    : "=r"(r0), "=r"(r1), "=r"(r2), "=r"(r3) : "r"(addr));
                bfr[nb * 2][0] = r0; bfr[nb * 2][1] = r1;
                bfr[nb * 2 + 1][0] = r2; bfr[nb * 2 + 1][1] = r3;
            }
#pragma unroll
            for (int mi = 0; mi < 4; ++mi)
#pragma unroll
                for (int ni = 0; ni < 4; ++ni)
                    asm volatile("mma.sync.aligned.m16n8k16.row.col.f32.bf16.bf16.f32 "
                        "{%0,%1,%2,%3},{%4,%5,%6,%7},{%8,%9},{%0,%1,%2,%3};\n"
                        : "+f"(acc[mi][ni][0]), "+f"(acc[mi][ni][1]),
                          "+f"(acc[mi][ni][2]), "+f"(acc[mi][ni][3])
                        : "r"(a[mi][0]), "r"(a[mi][1]), "r"(a[mi][2]), "r"(a[mi][3]),
                          "r"(bfr[ni][0]), "r"(bfr[ni][1]));
        }
    }

    float* Cb = g_cov + (size_t)b * W_ * W_;
    int g = lane >> 2, tg = lane & 3;
#pragma unroll
    for (int mi = 0; mi < 4; ++mi) {
        int m = bi * 128 + wm * 64 + mi * 16 + g;
#pragma unroll
        for (int ni = 0; ni < 4; ++ni) {
            int n2 = bj * 128 + wn * 32 + ni * 8 + tg * 2;
            *(float2*)(Cb + (size_t)m * W_ + n2)       = make_float2(acc[mi][ni][0], acc[mi][ni][1]);
            *(float2*)(Cb + (size_t)(m + 8) * W_ + n2) = make_float2(acc[mi][ni][2], acc[mi][ni][3]);
        }
    }
}

// ---------------- 4) rstd from Gram diagonal + rank-1 correction ----------------
__global__ __launch_bounds__(256) void rstd_kernel() {
    int i = blockIdx.x * 256 + threadIdx.x;    // 32768
    int b = i >> 10, w = i & 1023;
    float m = g_mean[i];
    float s = (g_cov[(size_t)b * W_ * W_ + (size_t)w * W_ + w] - (float)T_ * m * m) * INV_TM1;
    g_rstd[i] = (s > 0.f) ? rsqrtf(s) : 0.f;
}

// ---------------- 5) EMA scan over batches, upper pairs only (symmetric) ----------------
__global__ __launch_bounds__(256) void ema_kernel(const float* __restrict__ ema_in,
                                                  float* __restrict__ ema_out) {
    int v = blockIdx.x * 256 + threadIdx.x;
    int w = blockIdx.y;
    if (v < w) return;                          // corr/ema symmetric; mirror on write
    const float* cp = g_cov + (size_t)w * W_ + v;
    float e = __ldg(ema_in + w * W_ + v);
#pragma unroll 4
    for (int b = 0; b < B_; ++b) {
        float mw = g_mean[b * W_ + w], mv = g_mean[b * W_ + v];
        float c  = (__ldg(cp + (size_t)b * (W_ * W_)) - (float)T_ * mw * mv) * INV_TM1;
        float rw = g_rstd[b * W_ + w];
        float rv = g_rstd[b * W_ + v];
        float corr = c * rw * rv;
        corr = fminf(1.f, fmaxf(-1.f, corr));
        if (fabsf(corr) > 0.5f) e = 0.9f * e + 0.1f * corr;
    }
    ema_out[w * W_ + v] = e;
    ema_out[v * W_ + w] = e;
}

// ---------------- 6) per-(g,b) off-diagonal |corr| partial sums (diag tiles) ----------------
__global__ __launch_bounds__(256) void corr_partial_kernel() {
    int g = blockIdx.x, b = blockIdx.y;
    const float* covb = g_cov + (size_t)b * (W_ * W_);
    const float* rs   = g_rstd + b * W_;
    const float* mn   = g_mean + b * W_;
    int tid = threadIdx.x;
    float s = 0.f;
    for (int i = tid; i < D_ * D_; i += 256) {
        int d = i >> 6, e = i & 63;
        if (d == e) continue;
        int w = g * 64 + d, v = g * 64 + e;
        float c = (covb[(size_t)w * W_ + v] - (float)T_ * mn[w] * mn[v]) * INV_TM1;
        float corr = fminf(1.f, fmaxf(-1.f, c * rs[w] * rs[v]));
        s += fabsf(corr);
    }
    __shared__ float red[256];
    red[tid] = s;
    __syncthreads();
    for (int off = 128; off > 0; off >>= 1) {
        if (tid < off) red[tid] += red[tid + off];
        __syncthreads();
    }
    if (tid == 0) g_partial[b * G_ + g] = red[0];
}

__global__ void corr_final_kernel(float* __restrict__ out_corr) {
    int g = threadIdx.x;
    if (g < G_) {
        float s = 0.f;
        for (int b = 0; b < B_; ++b) s += g_partial[b * G_ + g];  // fixed order: deterministic
        out_corr[g] = s * (1.0f / ((float)(D_ * D_ - D_) * (float)B_));
    }
}

// ---------------- 7) expert MLP: D->16(relu)->1 per group ----------------
__global__ __launch_bounds__(256) void mlp_kernel(const float* __restrict__ x,
                                                  const float* __restrict__ W1,
                                                  const float* __restrict__ b1,
                                                  const float* __restrict__ W2,
                                                  const float* __restrict__ b2,
                                                  float* __restrict__ out) {
    __shared__ __align__(16) float W1s[4096];
    __shared__ float b1s[64], W2s[64], b2s[4];
    int tid = threadIdx.x;
    int gq = blockIdx.y;
    for (int i = tid; i < 1024; i += 256)
        ((float4*)W1s)[i] = ((const float4*)(W1 + (size_t)gq * 4096))[i];
    if (tid < 64) { b1s[tid] = b1[gq * 64 + tid]; W2s[tid] = W2[gq * 64 + tid]; }
    if (tid < 4) b2s[tid] = b2[gq * 4 + tid];
    __syncthreads();

    int gsub = tid & 3, tr = tid >> 2;
    int g = gq * 4 + gsub;
    size_t row0 = (size_t)blockIdx.x * 128 + tr * 2;
    const float4* xp0 = (const float4*)(x + row0 * W_ + g * 64);
    const float4* xp1 = (const float4*)(x + (row0 + 1) * W_ + g * 64);

    float h0[16], h1[16];
#pragma unroll
    for (int h = 0; h < 16; ++h) { h0[h] = b1s[gsub * 16 + h]; h1[h] = h0[h]; }

#pragma unroll 4
    for (int d4 = 0; d4 < 16; ++d4) {
        float4 xa = __ldg(xp0 + d4);
        float4 xb = __ldg(xp1 + d4);
#pragma unroll
        for (int h = 0; h < 16; ++h) {
            float4 wv = *(float4*)&W1s[(gsub * 16 + h) * 64 + d4 * 4];
            h0[h] = fmaf(wv.x, xa.x, h0[h]); h0[h] = fmaf(wv.y, xa.y, h0[h]);
            h0[h] = fmaf(wv.z, xa.z, h0[h]); h0[h] = fmaf(wv.w, xa.w, h0[h]);
            h1[h] = fmaf(wv.x, xb.x, h1[h]); h1[h] = fmaf(wv.y, xb.y, h1[h]);
            h1[h] = fmaf(wv.z, xb.z, h1[h]); h1[h] = fmaf(wv.w, xb.w, h1[h]);
        }
    }
    float o0 = b2s[gsub], o1 = b2s[gsub];
#pragma unroll
    for (int h = 0; h < 16; ++h) {
        o0 += W2s[gsub * 16 + h] * fmaxf(h0[h], 0.f);
        o1 += W2s[gsub * 16 + h] * fmaxf(h1[h], 0.f);
    }
    out[row0 * G_ + g]       = o0;
    out[(row0 + 1) * G_ + g] = o1;
}

// ---------------- launch ----------------
extern "C" void kernel_launch(void* const* d_in, const int* in_sizes, int n_in,
                              void* d_out, int out_size) {
    (void)in_sizes; (void)n_in; (void)out_size;
    const float* x   = (const float*)d_in[0];
    const float* ema = (const float*)d_in[1];
    const float* W1  = (const float*)d_in[2];
    const float* b1  = (const float*)d_in[3];
    const float* W2  = (const float*)d_in[4];
    const float* b2  = (const float*)d_in[5];

    float* out      = (float*)d_out;                      // (B,T,G) = 1048576
    float* out_corr = out + (size_t)B_ * T_ * G_;         // (G,)    = 16
    float* out_ema  = out_corr + G_;                      // (W,W)   = 1048576

    tobf16_kernel<<<(int)((size_t)B_ * T_ * W_ / 4 / 256), 256>>>(x);
    mean_kernel<<<dim3(W_ / 256, B_), 256>>>();
    cov_mma_kernel<<<dim3(36, B_), 256>>>();
    rstd_kernel<<<(B_ * W_) / 256, 256>>>();
    ema_kernel<<<dim3(W_ / 256, W_), 256>>>(ema, out_ema);
    corr_partial_kernel<<<dim3(G_, B_), 256>>>();
    corr_final_kernel<<<1, 32>>>(out_corr);
    mlp_kernel<<<dim3(B_ * T_ / 128, 4), 256>>>(x, W1, b1, W2, b2, out);
}